// round 8
// baseline (speedup 1.0000x reference)
#include <cuda_runtime.h>
#include <math.h>

#define V_ 50257
#define H_ 1024
#define E_ 1024
#define L_ 512
#define HE_ 2048
#define H3_ 3072

// ---------------------------------------------------------------------------
// Scratch (__device__ globals; no allocs allowed)
// Split-K partials: [split][row] flattened; consumer sums them.
// ---------------------------------------------------------------------------
__device__ float g_al2[2 * L_];      // attn logit partials (bias in split 0)
__device__ float g_attn_applied[H_];
__device__ float g_x2[2 * E_];       // combine partials (pre-bias, pre-relu)
__device__ float g_gi2[2 * H3_];     // w_ih gate partials
__device__ float g_gh2[2 * H3_];     // w_hh gate partials
__device__ float g_hnew[H_];
__device__ float g_S;                // sum of exp(logit)
__device__ unsigned g_cnt_d = 0;     // drain counter for k4

// ---------------------------------------------------------------------------
// helpers
// ---------------------------------------------------------------------------
__device__ __forceinline__ float warp_sum(float v) {
#pragma unroll
    for (int o = 16; o > 0; o >>= 1) v += __shfl_xor_sync(0xFFFFFFFFu, v, o);
    return v;
}
__device__ __forceinline__ float warp_max(float v) {
#pragma unroll
    for (int o = 16; o > 0; o >>= 1) v = fmaxf(v, __shfl_xor_sync(0xFFFFFFFFu, v, o));
    return v;
}
__device__ __forceinline__ float dot4(float4 a, float4 b) {
    return a.x * b.x + a.y * b.y + a.z * b.z + a.w * b.w;
}
__device__ __forceinline__ void ld_fence() { asm volatile("" ::: "memory"); }

// ---------------------------------------------------------------------------
// k1: fused independent front work, split-K=2.
//   blocks [0,128)   : attn_logits — warp w handles row=w/2, half=w&1
//   blocks [128,896) : w_hh @ hidden -> g_gh2 partials
// Also zeroes g_attn_applied / g_S.
// ---------------------------------------------------------------------------
__global__ void __launch_bounds__(256)
k1_front(const int* __restrict__ tok,
         const float* __restrict__ hidden,
         const float* __restrict__ emb_table,
         const float* __restrict__ attn_w,
         const float* __restrict__ attn_b,
         const float* __restrict__ w_hh) {
    __shared__ float4 sv[HE_ / 4];
    int t = threadIdx.x, lane = t & 31, wid = t >> 5;
    float* svf = (float*)sv;

    if (blockIdx.x < 4) g_attn_applied[blockIdx.x * 256 + t] = 0.f;
    if (blockIdx.x == 0 && t == 0) g_S = 0.f;

    if (blockIdx.x < 128) {
        // ---- attention logits (512 rows x 2 splits = 1024 warps) ----
        const float* e = emb_table + (size_t)tok[0] * E_;
        for (int i = t; i < E_; i += 256) { svf[i] = e[i]; svf[i + E_] = hidden[i]; }
        __syncthreads();

        int wg = blockIdx.x * 8 + wid;       // 0..1023
        int row = wg >> 1, split = wg & 1;
        int base = split * 256;              // float4 offset into 512-float4 row
        const float4* w = (const float4*)(attn_w + (size_t)row * HE_);
        float4 wv[8];
#pragma unroll
        for (int i = 0; i < 8; i++) wv[i] = w[base + lane + 32 * i];
        ld_fence();
        float s = 0.f;
#pragma unroll
        for (int i = 0; i < 8; i++) s += dot4(sv[base + lane + 32 * i], wv[i]);
        s = warp_sum(s);
        if (lane == 0) {
            if (split == 0) s += attn_b[row];
            g_al2[split * L_ + row] = s;
        }
    } else {
        // ---- w_hh @ hidden (3072 rows x 2 splits = 6144 warps) ----
        for (int i = t; i < H_; i += 256) svf[i] = hidden[i];
        __syncthreads();

        int wg = (blockIdx.x - 128) * 8 + wid;   // 0..6143
        int row = wg >> 1, split = wg & 1;
        int base = split * 128;                  // float4 offset into 256-float4 row
        const float4* w = (const float4*)(w_hh + (size_t)row * H_);
        float4 wv[4];
#pragma unroll
        for (int i = 0; i < 4; i++) wv[i] = w[base + lane + 32 * i];
        ld_fence();
        float s = 0.f;
#pragma unroll
        for (int i = 0; i < 4; i++) s += dot4(sv[base + lane + 32 * i], wv[i]);
        s = warp_sum(s);
        if (lane == 0) g_gh2[split * H3_ + row] = s;
    }
}

// ---------------------------------------------------------------------------
// k2: fused softmax(512) + attn_apply partials (atomicAdd tiles).
// grid=(8 h-groups, 8 l-splits), 128 threads. Sums logit partials first.
// ---------------------------------------------------------------------------
__global__ void k2_softmax_apply(const float* __restrict__ enc,
                                 float* __restrict__ out_aw) {
    __shared__ float red[4];
    __shared__ float stats[2];
    __shared__ float sw[64];
    int t = threadIdx.x, lane = t & 31, wid = t >> 5;

    float lv0 = g_al2[t]       + g_al2[L_ + t];
    float lv1 = g_al2[t + 128] + g_al2[L_ + t + 128];
    float lv2 = g_al2[t + 256] + g_al2[L_ + t + 256];
    float lv3 = g_al2[t + 384] + g_al2[L_ + t + 384];
    float m = fmaxf(fmaxf(lv0, lv1), fmaxf(lv2, lv3));
    m = warp_max(m);
    if (lane == 0) red[wid] = m;
    __syncthreads();
    if (t == 0) stats[0] = fmaxf(fmaxf(red[0], red[1]), fmaxf(red[2], red[3]));
    __syncthreads();
    float M = stats[0];
    float s = __expf(lv0 - M) + __expf(lv1 - M) + __expf(lv2 - M) + __expf(lv3 - M);
    s = warp_sum(s);
    __syncthreads();
    if (lane == 0) red[wid] = s;
    __syncthreads();
    if (t == 0) stats[1] = red[0] + red[1] + red[2] + red[3];
    __syncthreads();
    float S = stats[1];

    int l0 = blockIdx.y * 64;
    if (t < 64) {
        float lv = g_al2[l0 + t] + g_al2[L_ + l0 + t];
        sw[t] = __expf(lv - M) / S;
    }
    __syncthreads();

    int h = blockIdx.x * 128 + t;
    float acc = 0.f;
#pragma unroll 8
    for (int l = 0; l < 64; l++) acc += sw[l] * enc[(size_t)(l0 + l) * H_ + h];
    atomicAdd(&g_attn_applied[h], acc);

    if (blockIdx.x == 0 && blockIdx.y == 0) {
        out_aw[t]       = __expf(lv0 - M) / S;
        out_aw[t + 128] = __expf(lv1 - M) / S;
        out_aw[t + 256] = __expf(lv2 - M) / S;
        out_aw[t + 384] = __expf(lv3 - M) / S;
    }
}

// ---------------------------------------------------------------------------
// k3: combine partials, split-K=2 (1024 rows x 2 splits = 2048 warps).
// Writes raw partials; bias+relu folded into k4's staging read.
// ---------------------------------------------------------------------------
__global__ void __launch_bounds__(256)
k3_combine(const int* __restrict__ tok,
           const float* __restrict__ emb_table,
           const float* __restrict__ comb_w) {
    __shared__ float4 sv[HE_ / 4];
    int t = threadIdx.x, lane = t & 31, wid = t >> 5;

    const float* e = emb_table + (size_t)tok[0] * E_;
    float* svf = (float*)sv;
    for (int i = t; i < E_; i += 256) { svf[i] = e[i]; svf[i + E_] = g_attn_applied[i]; }
    __syncthreads();

    int wg = blockIdx.x * 8 + wid;       // 0..2047
    int row = wg >> 1, split = wg & 1;
    int base = split * 256;
    const float4* w = (const float4*)(comb_w + (size_t)row * HE_);
    float4 wv[8];
#pragma unroll
    for (int i = 0; i < 8; i++) wv[i] = w[base + lane + 32 * i];
    ld_fence();
    float s = 0.f;
#pragma unroll
    for (int i = 0; i < 8; i++) s += dot4(sv[base + lane + 32 * i], wv[i]);
    s = warp_sum(s);
    if (lane == 0) g_x2[split * E_ + row] = s;
}

// ---------------------------------------------------------------------------
// k4: w_ih @ x split-K=2 (6144 warps) + gate-math epilogue in last block.
// x reconstructed on stage: relu(p0+p1+comb_b).
// ---------------------------------------------------------------------------
__global__ void __launch_bounds__(256)
k4_gates(const float* __restrict__ w_ih,
         const float* __restrict__ comb_b,
         const float* __restrict__ b_ih,
         const float* __restrict__ b_hh,
         const float* __restrict__ hidden,
         float* __restrict__ out_h) {
    __shared__ float4 sv[H_ / 4];
    __shared__ bool isLast;
    int t = threadIdx.x, lane = t & 31, wid = t >> 5;

    float* svf = (float*)sv;
    for (int i = t; i < H_; i += 256)
        svf[i] = fmaxf(g_x2[i] + g_x2[E_ + i] + comb_b[i], 0.f);
    __syncthreads();

    int wg = blockIdx.x * 8 + wid;       // 0..6143
    int row = wg >> 1, split = wg & 1;
    int base = split * 128;
    const float4* w = (const float4*)(w_ih + (size_t)row * H_);
    float4 wv[4];
#pragma unroll
    for (int i = 0; i < 4; i++) wv[i] = w[base + lane + 32 * i];
    ld_fence();
    float s = 0.f;
#pragma unroll
    for (int i = 0; i < 4; i++) s += dot4(sv[base + lane + 32 * i], wv[i]);
    s = warp_sum(s);
    if (lane == 0) g_gi2[split * H3_ + row] = s;

    // last-block epilogue: gate math
    __threadfence();
    __syncthreads();
    if (t == 0) isLast = (atomicAdd(&g_cnt_d, 1u) == gridDim.x - 1);
    __syncthreads();
    if (!isLast) return;
    if (t == 0) g_cnt_d = 0;
    __threadfence();

#pragma unroll
    for (int h = t; h < H_; h += 256) {
        float ir = g_gi2[h]           + g_gi2[H3_ + h]           + b_ih[h];
        float iz = g_gi2[h + H_]      + g_gi2[H3_ + h + H_]      + b_ih[h + H_];
        float in = g_gi2[h + 2 * H_]  + g_gi2[H3_ + h + 2 * H_]  + b_ih[h + 2 * H_];
        float hr = g_gh2[h]           + g_gh2[H3_ + h]           + b_hh[h];
        float hz = g_gh2[h + H_]      + g_gh2[H3_ + h + H_]      + b_hh[h + H_];
        float hn = g_gh2[h + 2 * H_]  + g_gh2[H3_ + h + 2 * H_]  + b_hh[h + 2 * H_];
        float r = 1.f / (1.f + __expf(-(ir + hr)));
        float z = 1.f / (1.f + __expf(-(iz + hz)));
        float n = tanhf(in + r * hn);
        float hv = hidden[h];
        float hnew = (1.f - z) * n + z * hv;
        g_hnew[h] = hnew;
        out_h[h]  = hnew;
    }
}

// ---------------------------------------------------------------------------
// k5: logits GEMV — 512 threads, 16 rows/block (halves h_new re-reads).
// Writes raw logits; accumulates exp(logit) into g_S (logits tiny, no max).
// ---------------------------------------------------------------------------
__global__ void __launch_bounds__(512)
k5_logits(const float* __restrict__ out_w,
          const float* __restrict__ out_b,
          float* __restrict__ out_logits) {
    __shared__ float4 sh4[H_ / 4];
    __shared__ float red[16];
    int t = threadIdx.x, lane = t & 31, wid = t >> 5;
    if (t < H_ / 4) sh4[t] = ((const float4*)g_hnew)[t];
    __syncthreads();

    int row = blockIdx.x * 16 + wid;
    float part = 0.f;
    if (row < V_) {
        const float4* w = (const float4*)(out_w + (size_t)row * H_);
        float4 wv[8];
#pragma unroll
        for (int i = 0; i < 8; i++) wv[i] = w[lane + 32 * i];
        ld_fence();
        float s = 0.f;
#pragma unroll
        for (int i = 0; i < 8; i++) s += dot4(sh4[lane + 32 * i], wv[i]);
        s = warp_sum(s);
        if (lane == 0) {
            float logit = s + out_b[row];
            out_logits[row] = logit;
            part = __expf(logit);
        }
    }
    if (lane == 0) red[wid] = part;
    __syncthreads();
    if (t < 32) {
        float bs = (t < 16) ? red[t] : 0.f;
        bs = warp_sum(bs);
        if (t == 0) atomicAdd(&g_S, bs);
    }
}

// ---------------------------------------------------------------------------
// k6: out[v] -= log(sum exp)
// ---------------------------------------------------------------------------
__global__ void __launch_bounds__(512)
k6_finish(float* __restrict__ out_logits) {
    int v = blockIdx.x * blockDim.x + threadIdx.x;
    if (v >= V_) return;
    out_logits[v] = out_logits[v] - logf(g_S);
}

// ---------------------------------------------------------------------------
// launch
// ---------------------------------------------------------------------------
extern "C" void kernel_launch(void* const* d_in, const int* in_sizes, int n_in,
                              void* d_out, int out_size) {
    const int*   tok     = (const int*)  d_in[0];
    const float* hidden  = (const float*)d_in[1];
    const float* enc     = (const float*)d_in[2];
    const float* emb     = (const float*)d_in[3];
    const float* attn_w  = (const float*)d_in[4];
    const float* attn_b  = (const float*)d_in[5];
    const float* comb_w  = (const float*)d_in[6];
    const float* comb_b  = (const float*)d_in[7];
    const float* w_ih    = (const float*)d_in[8];
    const float* w_hh    = (const float*)d_in[9];
    const float* b_ih    = (const float*)d_in[10];
    const float* b_hh    = (const float*)d_in[11];
    const float* out_w   = (const float*)d_in[12];
    const float* out_b   = (const float*)d_in[13];

    float* out = (float*)d_out;
    float* out_logits = out;            // [V]
    float* out_h      = out + V_;       // [H]
    float* out_aw     = out + V_ + H_;  // [L]

    k1_front<<<896, 256>>>(tok, hidden, emb, attn_w, attn_b, w_hh);
    k2_softmax_apply<<<dim3(8, 8), 128>>>(enc, out_aw);
    k3_combine<<<256, 256>>>(tok, emb, comb_w);
    k4_gates<<<768, 256>>>(w_ih, comb_b, b_ih, b_hh, hidden, out_h);
    k5_logits<<<(V_ + 15) / 16, 512>>>(out_w, out_b, out_logits);
    k6_finish<<<(V_ + 511) / 512, 512>>>(out_logits);
}